// round 3
// baseline (speedup 1.0000x reference)
#include <cuda_runtime.h>
#include <math.h>

// Problem constants
#define B_ 64
#define T_ 512
#define D_ 512
#define H_ 1024
#define G_ 4096   // 4*H

// Scratch (device globals: allocation-free per harness rules)
__device__ float g_xw[(size_t)B_ * T_ * G_];   // precomputed x @ W_ih^T + bias, [B*T, 4H]
__device__ float g_hm[B_ * H_];                // h * hid_mask (recurrent input)
__device__ float g_c[B_ * H_];                 // cell state

// ---------------------------------------------------------------------------
// Init: zero h_masked and c
// ---------------------------------------------------------------------------
__global__ void k_init() {
    int i = blockIdx.x * blockDim.x + threadIdx.x;
    if (i < B_ * H_) { g_hm[i] = 0.f; g_c[i] = 0.f; }
}

// ---------------------------------------------------------------------------
// Input GEMM: g_xw[m, n] = sum_d x_masked[m, d] * W_ih[n, d] + (b_ih[n]+b_hh[n])
// m = b*T + t (row-major over x [B,T,D]); in_mask applied only when t == 0.
// 64x64 tile, BK=16, 256 threads, 4x4 register blocking.
// ---------------------------------------------------------------------------
__global__ __launch_bounds__(256) void k_input_gemm(
    const float* __restrict__ x, const float* __restrict__ Wih,
    const float* __restrict__ bih, const float* __restrict__ bhh,
    const float* __restrict__ in_mask)
{
    __shared__ float sA[16][68];
    __shared__ float sB[16][68];

    const int n0  = blockIdx.x * 64;
    const int m0  = blockIdx.y * 64;
    const int tid = threadIdx.x;
    const int lrow = tid >> 2;          // 0..63
    const int lc4  = (tid & 3) * 4;     // 0,4,8,12
    const int ty = tid >> 4;            // 0..15 (m sub-tile)
    const int tx = tid & 15;            // 0..15 (n sub-tile)

    float acc[4][4];
#pragma unroll
    for (int i = 0; i < 4; i++)
#pragma unroll
        for (int j = 0; j < 4; j++) acc[i][j] = 0.f;

    for (int kk = 0; kk < D_; kk += 16) {
        // Load A tile (x rows), transpose into sA[k][m]
        {
            const int m = m0 + lrow;
            float4 av = *(const float4*)(x + (size_t)m * D_ + kk + lc4);
            if ((m & (T_ - 1)) == 0) {  // t == 0 row: apply input dropout mask
                const float* im = in_mask + (m >> 9) * D_ + kk + lc4;
                av.x *= im[0]; av.y *= im[1]; av.z *= im[2]; av.w *= im[3];
            }
            sA[lc4 + 0][lrow] = av.x;
            sA[lc4 + 1][lrow] = av.y;
            sA[lc4 + 2][lrow] = av.z;
            sA[lc4 + 3][lrow] = av.w;
        }
        // Load B tile (W_ih rows), transpose into sB[k][n]
        {
            float4 bv = *(const float4*)(Wih + (size_t)(n0 + lrow) * D_ + kk + lc4);
            sB[lc4 + 0][lrow] = bv.x;
            sB[lc4 + 1][lrow] = bv.y;
            sB[lc4 + 2][lrow] = bv.z;
            sB[lc4 + 3][lrow] = bv.w;
        }
        __syncthreads();

#pragma unroll
        for (int k = 0; k < 16; k++) {
            float4 a = *(const float4*)&sA[k][ty * 4];
            float4 b = *(const float4*)&sB[k][tx * 4];
            acc[0][0] = fmaf(a.x, b.x, acc[0][0]);
            acc[0][1] = fmaf(a.x, b.y, acc[0][1]);
            acc[0][2] = fmaf(a.x, b.z, acc[0][2]);
            acc[0][3] = fmaf(a.x, b.w, acc[0][3]);
            acc[1][0] = fmaf(a.y, b.x, acc[1][0]);
            acc[1][1] = fmaf(a.y, b.y, acc[1][1]);
            acc[1][2] = fmaf(a.y, b.z, acc[1][2]);
            acc[1][3] = fmaf(a.y, b.w, acc[1][3]);
            acc[2][0] = fmaf(a.z, b.x, acc[2][0]);
            acc[2][1] = fmaf(a.z, b.y, acc[2][1]);
            acc[2][2] = fmaf(a.z, b.z, acc[2][2]);
            acc[2][3] = fmaf(a.z, b.w, acc[2][3]);
            acc[3][0] = fmaf(a.w, b.x, acc[3][0]);
            acc[3][1] = fmaf(a.w, b.y, acc[3][1]);
            acc[3][2] = fmaf(a.w, b.z, acc[3][2]);
            acc[3][3] = fmaf(a.w, b.w, acc[3][3]);
        }
        __syncthreads();
    }

    // Epilogue: add bias, store
    const int n = n0 + tx * 4;
    float bias0 = bih[n + 0] + bhh[n + 0];
    float bias1 = bih[n + 1] + bhh[n + 1];
    float bias2 = bih[n + 2] + bhh[n + 2];
    float bias3 = bih[n + 3] + bhh[n + 3];
#pragma unroll
    for (int i = 0; i < 4; i++) {
        const int m = m0 + ty * 4 + i;
        float4 o;
        o.x = acc[i][0] + bias0;
        o.y = acc[i][1] + bias1;
        o.z = acc[i][2] + bias2;
        o.w = acc[i][3] + bias3;
        *(float4*)(g_xw + (size_t)m * G_ + n) = o;
    }
}

// ---------------------------------------------------------------------------
// One LSTM timestep. Grid: 128 blocks (H/8 column tiles) x 256 threads.
// Block owns 8 hidden columns j0..j0+7 for ALL 64 batches and ALL 4 gates,
// so the pointwise LSTM update is fully thread-local.
// Thread: jl = tid&7 (column), b0 = (tid>>3)*2 (2 batches) -> 8 accumulators.
// ---------------------------------------------------------------------------
__global__ __launch_bounds__(256) void k_step(
    const float* __restrict__ Whh,
    const float* __restrict__ hid_mask,
    const float* __restrict__ out_mask,
    float* __restrict__ out, int t)
{
    __shared__ float sH[64][68];   // h_masked chunk: 64 batches x 64 k
    __shared__ float sW[32][68];   // 32 gate-rows (4 gates x 8 cols) x 64 k

    const int tid = threadIdx.x;
    const int j0  = blockIdx.x * 8;
    const int jl  = tid & 7;
    const int b0  = (tid >> 3) * 2;
    const int j   = j0 + jl;

    // Init accumulators from precomputed input projection (+bias)
    float acc[2][4];
#pragma unroll
    for (int bb = 0; bb < 2; bb++)
#pragma unroll
        for (int g = 0; g < 4; g++)
            acc[bb][g] = g_xw[(size_t)((b0 + bb) * T_ + t) * G_ + g * H_ + j];

    for (int kk = 0; kk < H_; kk += 64) {
        // Load h chunk: 64x64 floats = 1024 float4, 4 per thread
#pragma unroll
        for (int i = 0; i < 4; i++) {
            int v = tid + 256 * i;
            int r = v >> 4;
            int c = (v & 15) * 4;
            *(float4*)&sH[r][c] = *(const float4*)(g_hm + r * H_ + kk + c);
        }
        // Load W chunk: 32x64 floats = 512 float4, 2 per thread
#pragma unroll
        for (int i = 0; i < 2; i++) {
            int v = tid + 256 * i;
            int r = v >> 4;                       // local row 0..31 = g*8 + col
            int c = (v & 15) * 4;
            int grow = (r >> 3) * H_ + j0 + (r & 7);
            *(float4*)&sW[r][c] = *(const float4*)(Whh + (size_t)grow * H_ + kk + c);
        }
        __syncthreads();

#pragma unroll
        for (int k = 0; k < 64; k += 4) {
            float4 h0 = *(const float4*)&sH[b0][k];
            float4 h1 = *(const float4*)&sH[b0 + 1][k];
#pragma unroll
            for (int g = 0; g < 4; g++) {
                float4 w = *(const float4*)&sW[g * 8 + jl][k];
                acc[0][g] = fmaf(h0.w, w.w, fmaf(h0.z, w.z,
                            fmaf(h0.y, w.y, fmaf(h0.x, w.x, acc[0][g]))));
                acc[1][g] = fmaf(h1.w, w.w, fmaf(h1.z, w.z,
                            fmaf(h1.y, w.y, fmaf(h1.x, w.x, acc[1][g]))));
            }
        }
        __syncthreads();
    }

    // Pointwise LSTM update (PyTorch gate order i, f, g, o)
#pragma unroll
    for (int bb = 0; bb < 2; bb++) {
        const int b   = b0 + bb;
        const int idx = b * H_ + j;
        float iv = 1.f / (1.f + expf(-acc[bb][0]));
        float fv = 1.f / (1.f + expf(-acc[bb][1]));
        float gv = tanhf(acc[bb][2]);
        float ov = 1.f / (1.f + expf(-acc[bb][3]));
        float cn = fmaf(fv, g_c[idx], iv * gv);
        float hn = ov * tanhf(cn);
        g_c[idx] = cn;
        float hm = hn * hid_mask[idx];
        g_hm[idx] = hm;
        out[(size_t)(b * T_ + t) * H_ + j] = hn * out_mask[idx];
        if (t == T_ - 1) {
            // h_f = h_n * hid_mask (the scan carry), c_f = c_n
            out[(size_t)B_ * T_ * H_ + idx] = hm;
            out[(size_t)B_ * T_ * H_ + (size_t)B_ * H_ + idx] = cn;
        }
    }
}

// ---------------------------------------------------------------------------
// Launch: init + input GEMM + 512 sequential step kernels (stream-ordered,
// graph-capturable: kernel launches only).
// ---------------------------------------------------------------------------
extern "C" void kernel_launch(void* const* d_in, const int* in_sizes, int n_in,
                              void* d_out, int out_size)
{
    const float* x        = (const float*)d_in[0];
    const float* Wih      = (const float*)d_in[1];
    const float* Whh      = (const float*)d_in[2];
    const float* bih      = (const float*)d_in[3];
    const float* bhh      = (const float*)d_in[4];
    const float* in_mask  = (const float*)d_in[5];
    const float* hid_mask = (const float*)d_in[6];
    const float* out_mask = (const float*)d_in[7];
    float* out = (float*)d_out;

    k_init<<<(B_ * H_ + 255) / 256, 256>>>();
    k_input_gemm<<<dim3(G_ / 64, (B_ * T_) / 64), 256>>>(x, Wih, bih, bhh, in_mask);
    for (int t = 0; t < T_; t++)
        k_step<<<H_ / 8, 256>>>(Whh, hid_mask, out_mask, out, t);
}

// round 5
// speedup vs baseline: 1.1207x; 1.1207x over previous
#include <cuda_runtime.h>
#include <math.h>

// Problem constants
#define B_ 64
#define T_ 512
#define D_ 512
#define H_ 1024
#define G_ 4096           // 4*H
#define KSPLIT 16
#define NBLK 128          // persistent grid size (<= 148 SMs, 1 block/SM)

// Device-global scratch (allocation-free per harness rules)
__device__ float g_xw[(size_t)B_ * T_ * G_];   // x @ W_ih^T + bias  [B*T, 4H]
__device__ float g_hmT[H_ * B_];               // h*hid_mask, TRANSPOSED [j][b]
__device__ float g_c[B_ * H_];                 // cell state [b][j]
__device__ float g_part[KSPLIT][B_][G_];       // split-k partials (16 MB)
__device__ unsigned int g_bar;                 // grid barrier counter

// ---------------- f32x2 packed-FMA helpers (Blackwell FFMA2) ----------------
__device__ __forceinline__ unsigned long long pk2(float x, float y) {
    unsigned long long r;
    asm("mov.b64 %0, {%1, %2};" : "=l"(r) : "f"(x), "f"(y));
    return r;
}
__device__ __forceinline__ unsigned long long dup2(float x) {
    unsigned long long r;
    asm("mov.b64 %0, {%1, %1};" : "=l"(r) : "f"(x));
    return r;
}
__device__ __forceinline__ void fma2(unsigned long long& c,
                                     unsigned long long a, unsigned long long b) {
    asm("fma.rn.f32x2 %0, %1, %2, %0;" : "+l"(c) : "l"(a), "l"(b));
}
__device__ __forceinline__ float2 upk2(unsigned long long v) {
    float2 f;
    asm("mov.b64 {%0, %1}, %2;" : "=f"(f.x), "=f"(f.y) : "l"(v));
    return f;
}

// ---------------------------------------------------------------------------
// Init: zero recurrent state + barrier
// ---------------------------------------------------------------------------
__global__ void k_init() {
    int i = blockIdx.x * blockDim.x + threadIdx.x;
    if (i < B_ * H_) { g_hmT[i] = 0.f; g_c[i] = 0.f; }
    if (i == 0) g_bar = 0u;
}

// ---------------------------------------------------------------------------
// Input GEMM (FFMA2): g_xw[m,n] = sum_d x_masked[m,d]*W_ih[n,d] + bias[n]
// 128x128 tile, BK=16, 256 threads, 8x8 per thread (f32x2 pairs over n).
// ---------------------------------------------------------------------------
__global__ __launch_bounds__(256, 2) void k_igemm(
    const float* __restrict__ x, const float* __restrict__ Wih,
    const float* __restrict__ bih, const float* __restrict__ bhh,
    const float* __restrict__ in_mask)
{
    __shared__ float sA[16][132];   // [k][m]
    __shared__ float sB[16][132];   // [k][n]

    const int n0  = blockIdx.x * 128;
    const int m0  = blockIdx.y * 128;
    const int tid = threadIdx.x;
    const int tx  = tid & 15;
    const int ty  = tid >> 4;

    unsigned long long acc[8][4];   // [m i][n-pair]
#pragma unroll
    for (int i = 0; i < 8; i++)
#pragma unroll
        for (int j = 0; j < 4; j++) acc[i][j] = 0ull;

    for (int kk = 0; kk < D_; kk += 16) {
#pragma unroll
        for (int i = 0; i < 2; i++) {
            int v = tid + i * 256;
            int row = v >> 2;
            int kq  = (v & 3) * 4;
            int m   = m0 + row;
            float4 av = *(const float4*)(x + (size_t)m * D_ + kk + kq);
            if ((m & (T_ - 1)) == 0) {
                const float* im = in_mask + (m >> 9) * D_ + kk + kq;
                av.x *= im[0]; av.y *= im[1]; av.z *= im[2]; av.w *= im[3];
            }
            sA[kq + 0][row] = av.x;
            sA[kq + 1][row] = av.y;
            sA[kq + 2][row] = av.z;
            sA[kq + 3][row] = av.w;
        }
#pragma unroll
        for (int i = 0; i < 2; i++) {
            int v = tid + i * 256;
            int row = v >> 2;
            int kq  = (v & 3) * 4;
            float4 bv = *(const float4*)(Wih + (size_t)(n0 + row) * D_ + kk + kq);
            sB[kq + 0][row] = bv.x;
            sB[kq + 1][row] = bv.y;
            sB[kq + 2][row] = bv.z;
            sB[kq + 3][row] = bv.w;
        }
        __syncthreads();

#pragma unroll
        for (int k = 0; k < 16; k++) {
            float4 a0 = *(const float4*)&sA[k][ty * 4];
            float4 a1 = *(const float4*)&sA[k][64 + ty * 4];
            ulonglong2 b0 = *(const ulonglong2*)&sB[k][tx * 4];
            ulonglong2 b1 = *(const ulonglong2*)&sB[k][64 + tx * 4];
            unsigned long long ad[8];
            ad[0] = dup2(a0.x); ad[1] = dup2(a0.y);
            ad[2] = dup2(a0.z); ad[3] = dup2(a0.w);
            ad[4] = dup2(a1.x); ad[5] = dup2(a1.y);
            ad[6] = dup2(a1.z); ad[7] = dup2(a1.w);
#pragma unroll
            for (int i = 0; i < 8; i++) {
                fma2(acc[i][0], ad[i], b0.x);
                fma2(acc[i][1], ad[i], b0.y);
                fma2(acc[i][2], ad[i], b1.x);
                fma2(acc[i][3], ad[i], b1.y);
            }
        }
        __syncthreads();
    }

    const int nA = n0 + tx * 4;
    const int nB = n0 + 64 + tx * 4;
    float4 biasA = make_float4(bih[nA+0]+bhh[nA+0], bih[nA+1]+bhh[nA+1],
                               bih[nA+2]+bhh[nA+2], bih[nA+3]+bhh[nA+3]);
    float4 biasB = make_float4(bih[nB+0]+bhh[nB+0], bih[nB+1]+bhh[nB+1],
                               bih[nB+2]+bhh[nB+2], bih[nB+3]+bhh[nB+3]);
#pragma unroll
    for (int i = 0; i < 8; i++) {
        int m = m0 + ((i < 4) ? ty * 4 + i : 64 + ty * 4 + (i - 4));
        float2 p0 = upk2(acc[i][0]);
        float2 p1 = upk2(acc[i][1]);
        float2 p2 = upk2(acc[i][2]);
        float2 p3 = upk2(acc[i][3]);
        *(float4*)(g_xw + (size_t)m * G_ + nA) =
            make_float4(p0.x + biasA.x, p0.y + biasA.y, p1.x + biasA.z, p1.y + biasA.w);
        *(float4*)(g_xw + (size_t)m * G_ + nB) =
            make_float4(p2.x + biasB.x, p2.y + biasB.y, p3.x + biasB.z, p3.y + biasB.w);
    }
}

// ---------------------------------------------------------------------------
// Grid barrier: release (threadfence by every thread) + arrive/spin (thread 0)
// ---------------------------------------------------------------------------
__device__ __forceinline__ void gsync(unsigned int& tgt) {
    __threadfence();
    __syncthreads();
    if (threadIdx.x == 0) {
        atomicAdd(&g_bar, 1u);
        tgt += NBLK;
        while (*(volatile unsigned int*)&g_bar < tgt) { __nanosleep(32); }
        __threadfence();
    }
    __syncthreads();
}

// ---------------------------------------------------------------------------
// Persistent recurrence kernel. Grid = 128 blocks x 256 threads, 1 block/SM.
// Block task (fixed for all 512 steps): row-tile rt = bid>>4 (512 gate-rows),
// k-seg ks = bid&15 (64 k). W slice (512x64 = 132KB) cached in smem ONCE.
// Phase A: partial GEMM 64 batches x 512 rows x 64 k -> g_part[ks].
// Phase B: all blocks reduce 16 partials + xw, pointwise, update state.
// ---------------------------------------------------------------------------
#define SWPAD 516
#define SHPAD 68
#define SMEM_FLOATS (64 * SWPAD + 64 * SHPAD)

__global__ __launch_bounds__(256, 1) void k_persist(
    const float* __restrict__ Whh,
    const float* __restrict__ hid_mask,
    const float* __restrict__ out_mask,
    float* __restrict__ out)
{
    extern __shared__ float smem[];
    float* sW = smem;                 // [64 k][512 rows +pad]
    float* sH = smem + 64 * SWPAD;    // [64 k][64 b +pad]

    const int tid = threadIdx.x;
    const int bid = blockIdx.x;
    const int rt  = bid >> 4;         // 0..7 : rows [rt*512, rt*512+512)
    const int ks  = bid & 15;         // 0..15: k in [ks*64, ks*64+64)
    const int r0  = rt * 512;
    const int kb  = ks * 64;
    const int tx  = tid & 31;         // row group (16 rows: 4 quads of 4)
    const int ty  = tid >> 5;         // batch group (8 batches)

    // ---- Preload W slice into smem (once) ----
#pragma unroll
    for (int i = 0; i < 32; i++) {
        int v   = tid + i * 256;       // 0..8191
        int row = v >> 4;              // 0..511
        int kq  = (v & 15) * 4;
        float4 wv = *(const float4*)(Whh + (size_t)(r0 + row) * H_ + kb + kq);
        sW[(kq + 0) * SWPAD + row] = wv.x;
        sW[(kq + 1) * SWPAD + row] = wv.y;
        sW[(kq + 2) * SWPAD + row] = wv.z;
        sW[(kq + 3) * SWPAD + row] = wv.w;
    }

    unsigned int tgt = 0;
    float* gp = &g_part[ks][0][0];

    for (int t = 0; t < T_; t++) {
        // ---- Phase A: stage h slice, then partial GEMM ----
        __syncthreads();   // protect sH from previous iteration's readers
#pragma unroll
        for (int i = 0; i < 4; i++) {
            int v  = tid + i * 256;    // 0..1023
            int kk = v >> 4;           // 0..63
            int bq = (v & 15) * 4;
            float4 hv = __ldcg((const float4*)(g_hmT + (kb + kk) * B_ + bq));
            *(float4*)&sH[kk * SHPAD + bq] = hv;
        }
        __syncthreads();

        unsigned long long acc[8][8];  // [batch i][row-pair p]
#pragma unroll
        for (int i = 0; i < 8; i++)
#pragma unroll
            for (int p = 0; p < 8; p++) acc[i][p] = 0ull;

#pragma unroll 4
        for (int k = 0; k < 64; k++) {
            const float* swr = sW + k * SWPAD;
            float4 h0 = *(const float4*)&sH[k * SHPAD + ty * 8];
            float4 h1 = *(const float4*)&sH[k * SHPAD + ty * 8 + 4];
            ulonglong2 w0 = *(const ulonglong2*)&swr[tx * 4];
            ulonglong2 w1 = *(const ulonglong2*)&swr[128 + tx * 4];
            ulonglong2 w2 = *(const ulonglong2*)&swr[256 + tx * 4];
            ulonglong2 w3 = *(const ulonglong2*)&swr[384 + tx * 4];
            unsigned long long hd[8];
            hd[0] = dup2(h0.x); hd[1] = dup2(h0.y);
            hd[2] = dup2(h0.z); hd[3] = dup2(h0.w);
            hd[4] = dup2(h1.x); hd[5] = dup2(h1.y);
            hd[6] = dup2(h1.z); hd[7] = dup2(h1.w);
#pragma unroll
            for (int i = 0; i < 8; i++) {
                fma2(acc[i][0], hd[i], w0.x);
                fma2(acc[i][1], hd[i], w0.y);
                fma2(acc[i][2], hd[i], w1.x);
                fma2(acc[i][3], hd[i], w1.y);
                fma2(acc[i][4], hd[i], w2.x);
                fma2(acc[i][5], hd[i], w2.y);
                fma2(acc[i][6], hd[i], w3.x);
                fma2(acc[i][7], hd[i], w3.y);
            }
        }

        // Store partials (pairs are adjacent rows -> contiguous 16B stores)
#pragma unroll
        for (int i = 0; i < 8; i++) {
            int b = ty * 8 + i;
            float* dst = gp + (size_t)b * G_ + r0 + tx * 4;
            ulonglong2 s;
            s.x = acc[i][0]; s.y = acc[i][1]; *(ulonglong2*)(dst)       = s;
            s.x = acc[i][2]; s.y = acc[i][3]; *(ulonglong2*)(dst + 128) = s;
            s.x = acc[i][4]; s.y = acc[i][5]; *(ulonglong2*)(dst + 256) = s;
            s.x = acc[i][6]; s.y = acc[i][7]; *(ulonglong2*)(dst + 384) = s;
        }

        gsync(tgt);

        // ---- Phase B: reduce + pointwise (2 elements per thread) ----
#pragma unroll
        for (int u = 0; u < 2; u++) {
            int gidx = bid * 256 + tid + u * (NBLK * 256);  // 0..65535
            int b = gidx >> 10;
            int j = gidx & 1023;

            float s0 = g_xw[((size_t)(b * T_ + t)) * G_ + 0 * H_ + j];
            float s1 = g_xw[((size_t)(b * T_ + t)) * G_ + 1 * H_ + j];
            float s2 = g_xw[((size_t)(b * T_ + t)) * G_ + 2 * H_ + j];
            float s3 = g_xw[((size_t)(b * T_ + t)) * G_ + 3 * H_ + j];
#pragma unroll
            for (int kz = 0; kz < KSPLIT; kz++) {
                const float* pb = &g_part[kz][b][0];
                s0 += __ldcg(pb + 0 * H_ + j);
                s1 += __ldcg(pb + 1 * H_ + j);
                s2 += __ldcg(pb + 2 * H_ + j);
                s3 += __ldcg(pb + 3 * H_ + j);
            }

            const int hidx = b * H_ + j;
            float i_ = 1.f / (1.f + expf(-s0));
            float f_ = 1.f / (1.f + expf(-s1));
            float gg = tanhf(s2);
            float o_ = 1.f / (1.f + expf(-s3));
            float cn = fmaf(f_, g_c[hidx], i_ * gg);
            float hn = o_ * tanhf(cn);
            float hm = hn * hid_mask[hidx];
            g_c[hidx]           = cn;
            g_hmT[j * B_ + b]   = hm;
            out[((size_t)(b * T_ + t)) * H_ + j] = hn * out_mask[hidx];
            if (t == T_ - 1) {
                out[(size_t)B_ * T_ * H_ + hidx] = hm;                       // h_f
                out[(size_t)B_ * T_ * H_ + (size_t)B_ * H_ + hidx] = cn;     // c_f
            }
        }

        gsync(tgt);
    }
}

// ---------------------------------------------------------------------------
// Launch: 3 graph nodes total (fixes R4's node-count-induced teardown leak).
// ---------------------------------------------------------------------------
extern "C" void kernel_launch(void* const* d_in, const int* in_sizes, int n_in,
                              void* d_out, int out_size)
{
    const float* x        = (const float*)d_in[0];
    const float* Wih      = (const float*)d_in[1];
    const float* Whh      = (const float*)d_in[2];
    const float* bih      = (const float*)d_in[3];
    const float* bhh      = (const float*)d_in[4];
    const float* in_mask  = (const float*)d_in[5];
    const float* hid_mask = (const float*)d_in[6];
    const float* out_mask = (const float*)d_in[7];
    float* out = (float*)d_out;

    static int smem_set = 0;
    if (!smem_set) {
        cudaFuncSetAttribute(k_persist, cudaFuncAttributeMaxDynamicSharedMemorySize,
                             SMEM_FLOATS * sizeof(float));
        smem_set = 1;
    }

    k_init<<<(B_ * H_ + 255) / 256, 256>>>();
    k_igemm<<<dim3(G_ / 128, (B_ * T_) / 128), 256>>>(x, Wih, bih, bhh, in_mask);
    k_persist<<<NBLK, 256, SMEM_FLOATS * sizeof(float)>>>(Whh, hid_mask, out_mask, out);
}

// round 8
// speedup vs baseline: 1.8893x; 1.6858x over previous
#include <cuda_runtime.h>
#include <cuda_bf16.h>
#include <math.h>
#include <stdint.h>

// Problem constants
#define B_ 64
#define T_ 512
#define D_ 512
#define H_ 1024
#define G_ 4096           // 4*H
#define KS_ 4             // k-split for recurrence
#define KB_ 256           // k per recurrence block (H_/KS_)
#define NBLK 128          // persistent grid (1 block/SM, all resident)

// Device-global scratch (allocation-free per harness rules)
__device__ float g_xw[(size_t)B_ * T_ * G_];   // x @ W_ih^T + bias  [b*T+t][4H]
__device__ float g_hm[B_ * H_];                // h * hid_mask  [b][j]
__device__ float g_c[B_ * H_];                 // cell state    [b][j]
__device__ float g_part[KS_][G_][B_];          // split-k partials [ks][rowc][b]
__device__ unsigned int g_bar;

// ---------------------------- helpers --------------------------------------
__device__ __forceinline__ uint32_t smem_u32(const void* p) {
    uint32_t a;
    asm("{ .reg .u64 t; cvta.to.shared.u64 t, %1; cvt.u32.u64 %0, t; }"
        : "=r"(a) : "l"(p));
    return a;
}
// Split-2 bf16: v = hi + lo (lo itself bf16-rounded); packs pairs (a,b)
__device__ __forceinline__ void split2(float a, float b, uint32_t& hi, uint32_t& lo) {
    __nv_bfloat16 ah = __float2bfloat16(a);
    __nv_bfloat16 bh = __float2bfloat16(b);
    float la = a - __bfloat162float(ah);
    float lb = b - __bfloat162float(bh);
    __nv_bfloat162 h2 = __floats2bfloat162_rn(a, b);
    __nv_bfloat162 l2 = __floats2bfloat162_rn(la, lb);
    hi = *(uint32_t*)&h2;
    lo = *(uint32_t*)&l2;
}
__device__ __forceinline__ void ldm4(uint32_t addr, uint32_t r[4]) {
    asm volatile("ldmatrix.sync.aligned.m8n8.x4.shared.b16 {%0,%1,%2,%3}, [%4];"
        : "=r"(r[0]), "=r"(r[1]), "=r"(r[2]), "=r"(r[3]) : "r"(addr));
}
__device__ __forceinline__ void mma16816(float c[4], const uint32_t a[4],
                                         const uint32_t b[2]) {
    asm volatile(
        "mma.sync.aligned.m16n8k16.row.col.f32.bf16.bf16.f32 "
        "{%0,%1,%2,%3}, {%4,%5,%6,%7}, {%8,%9}, {%0,%1,%2,%3};"
        : "+f"(c[0]), "+f"(c[1]), "+f"(c[2]), "+f"(c[3])
        : "r"(a[0]), "r"(a[1]), "r"(a[2]), "r"(a[3]), "r"(b[0]), "r"(b[1]));
}

// ---------------------------------------------------------------------------
// Init: zero recurrent state + barrier
// ---------------------------------------------------------------------------
__global__ void k_init() {
    int i = blockIdx.x * blockDim.x + threadIdx.x;
    if (i < B_ * H_) { g_hm[i] = 0.f; g_c[i] = 0.f; }
    if (i == 0) g_bar = 0u;
}

// ---------------------------------------------------------------------------
// Input GEMM (HMMA, split-2 bf16):
//   g_xw[m,n] = sum_d x_masked[m,d] * W_ih[n,d] + (b_ih+b_hh)[n]
// Block: 256 thr (8 warps), tile M=128 x N=128, K chunks of 64 (8 chunks).
// Warp tile 64m x 32n = 4x4 m16n8k16 tiles. 3 split passes.
// SMEM tiles row-major [row][k], bf16, row stride 72 (144B: conflict-free ldmatrix).
// ---------------------------------------------------------------------------
#define IG_AH   0
#define IG_AL   18432
#define IG_BH   36864
#define IG_BL   55296
#define IG_BIAS 73728
#define IG_SMEM 74240

__global__ __launch_bounds__(256, 1) void k_igemm(
    const float* __restrict__ x, const float* __restrict__ Wih,
    const float* __restrict__ bih, const float* __restrict__ bhh,
    const float* __restrict__ in_mask)
{
    extern __shared__ __align__(16) char smem[];
    const uint32_t sb = smem_u32(smem);
    const int tid = threadIdx.x;
    const int l   = tid & 31;
    const int w   = tid >> 5;
    const int wy  = w >> 2;         // 0..1 (m half)
    const int wx  = w & 3;          // 0..3 (n quarter)
    const int n0  = blockIdx.x * 128;
    const int m0  = blockIdx.y * 128;

    float* sBias = (float*)(smem + IG_BIAS);
    if (tid < 128) sBias[tid] = bih[n0 + tid] + bhh[n0 + tid];

    // ldmatrix lane-address components
    const int rA = ((l >> 3) & 1) * 8 + (l & 7);
    const int kA = (l >> 4) * 8;
    const int nB = ((l >> 4) & 1) * 8 + (l & 7);
    const int kB = ((l >> 3) & 1) * 8;
    const uint32_t aOff = (uint32_t)(((wy * 64 + rA) * 72 + kA) * 2);
    const uint32_t bOff = (uint32_t)(((wx * 32 + nB) * 72 + kB) * 2);

    float acc[4][4][4] = {};

    for (int ch = 0; ch < 8; ch++) {
        const int kk = ch * 64;
        __syncthreads();
        // Stage x tile: 128 rows x 64 k -> hi/lo
#pragma unroll
        for (int i = 0; i < 8; i++) {
            int v = tid + i * 256;
            int r = v >> 4;
            int kq = (v & 15) * 4;
            int m = m0 + r;
            float4 xv = *(const float4*)(x + (size_t)m * D_ + kk + kq);
            if ((m & (T_ - 1)) == 0) {
                const float* im = in_mask + (m >> 9) * D_ + kk + kq;
                xv.x *= im[0]; xv.y *= im[1]; xv.z *= im[2]; xv.w *= im[3];
            }
            uint32_t h0, l0, h1, l1;
            split2(xv.x, xv.y, h0, l0);
            split2(xv.z, xv.w, h1, l1);
            uint32_t off = (uint32_t)((r * 72 + kq) * 2);
            *(uint2*)(smem + IG_AH + off) = make_uint2(h0, h1);
            *(uint2*)(smem + IG_AL + off) = make_uint2(l0, l1);
        }
        // Stage Wih tile: 128 rows x 64 k -> hi/lo
#pragma unroll
        for (int i = 0; i < 8; i++) {
            int v = tid + i * 256;
            int r = v >> 4;
            int kq = (v & 15) * 4;
            float4 wv = *(const float4*)(Wih + (size_t)(n0 + r) * D_ + kk + kq);
            uint32_t h0, l0, h1, l1;
            split2(wv.x, wv.y, h0, l0);
            split2(wv.z, wv.w, h1, l1);
            uint32_t off = (uint32_t)((r * 72 + kq) * 2);
            *(uint2*)(smem + IG_BH + off) = make_uint2(h0, h1);
            *(uint2*)(smem + IG_BL + off) = make_uint2(l0, l1);
        }
        __syncthreads();

#pragma unroll
        for (int pass = 0; pass < 3; pass++) {
            uint32_t aBase = sb + ((pass == 1) ? IG_AL : IG_AH) + aOff;
            uint32_t bBase = sb + ((pass == 2) ? IG_BL : IG_BH) + bOff;
#pragma unroll
            for (int ks = 0; ks < 4; ks++) {
                uint32_t af[4][4];
#pragma unroll
                for (int mt = 0; mt < 4; mt++)
                    ldm4(aBase + mt * 2304 + ks * 32, af[mt]);
                uint32_t bf[4][2];
#pragma unroll
                for (int p = 0; p < 2; p++) {
                    uint32_t r4[4];
                    ldm4(bBase + p * 2304 + ks * 32, r4);
                    bf[p * 2][0] = r4[0]; bf[p * 2][1] = r4[1];
                    bf[p * 2 + 1][0] = r4[2]; bf[p * 2 + 1][1] = r4[3];
                }
#pragma unroll
                for (int mt = 0; mt < 4; mt++)
#pragma unroll
                    for (int nt = 0; nt < 4; nt++)
                        mma16816(acc[mt][nt], af[mt], bf[nt]);
            }
        }
    }

    // Epilogue: bias + store (thread holds rows l/4, l/4+8; col pair (l&3)*2)
#pragma unroll
    for (int mt = 0; mt < 4; mt++) {
        int mrow = m0 + wy * 64 + mt * 16 + (l >> 2);
#pragma unroll
        for (int nt = 0; nt < 4; nt++) {
            int nl = wx * 32 + nt * 8 + (l & 3) * 2;
            float b0 = sBias[nl], b1 = sBias[nl + 1];
            *(float2*)(g_xw + (size_t)mrow * G_ + n0 + nl) =
                make_float2(acc[mt][nt][0] + b0, acc[mt][nt][1] + b1);
            *(float2*)(g_xw + (size_t)(mrow + 8) * G_ + n0 + nl) =
                make_float2(acc[mt][nt][2] + b0, acc[mt][nt][3] + b1);
        }
    }
}

// ---------------------------------------------------------------------------
// Grid barrier
// ---------------------------------------------------------------------------
__device__ __forceinline__ void gsync(unsigned int& tgt) {
    __threadfence();
    __syncthreads();
    if (threadIdx.x == 0) {
        atomicAdd(&g_bar, 1u);
        tgt += NBLK;
        while (*(volatile unsigned int*)&g_bar < tgt) { __nanosleep(64); }
        __threadfence();
    }
    __syncthreads();
}

// ---------------------------------------------------------------------------
// Persistent recurrence (HMMA). Grid 128 blocks x 128 threads (4 warps).
// Block (rt = bid>>2, ks = bid&3): A = 128 gathered gate-rows
//   grow(lr) = (lr>>5)*H + rt*32 + (lr&31),  k-slice [ks*256, +256).
// W slice converted to bf16 hi/lo SMEM ONCE (132 KB, resident all steps).
// Per step: stage h hi/lo (66KB) -> 768 MMA/warp -> partials -> gsync
//           -> reduce(4)+pointwise for j in [rt*32+ks*8, +8) -> gsync.
// SMEM row stride 264 bf16 (528B): conflict-free ldmatrix.
// ---------------------------------------------------------------------------
#define PSS     264
#define PS_WH   0
#define PS_WL   67584
#define PS_HH   135168
#define PS_HL   168960
#define PS_SMEM 202752

__global__ __launch_bounds__(128, 1) void k_persist(
    const float* __restrict__ Whh,
    const float* __restrict__ hid_mask,
    const float* __restrict__ out_mask,
    float* __restrict__ out)
{
    extern __shared__ __align__(16) char smem[];
    const uint32_t sb = smem_u32(smem);
    const int tid = threadIdx.x;
    const int l   = tid & 31;
    const int w   = tid >> 5;
    const int bid = blockIdx.x;
    const int rt  = bid >> 2;
    const int ks  = bid & 3;
    const int kb  = ks * KB_;

    // ---- Convert + stage W slice once: 128 gathered rows x 256 k ----
#pragma unroll
    for (int i = 0; i < 64; i++) {
        int v  = tid + i * 128;            // 0..8191
        int lr = v >> 6;                   // 0..127
        int kq = (v & 63) * 4;             // 0..252
        int grow = (lr >> 5) * H_ + rt * 32 + (lr & 31);
        float4 wv = *(const float4*)(Whh + (size_t)grow * H_ + kb + kq);
        uint32_t h0, l0, h1, l1;
        split2(wv.x, wv.y, h0, l0);
        split2(wv.z, wv.w, h1, l1);
        uint32_t off = (uint32_t)((lr * PSS + kq) * 2);
        *(uint2*)(smem + PS_WH + off) = make_uint2(h0, h1);
        *(uint2*)(smem + PS_WL + off) = make_uint2(l0, l1);
    }

    // ldmatrix lane-address components
    const int rA = ((l >> 3) & 1) * 8 + (l & 7);
    const int kA = (l >> 4) * 8;
    const int nB = ((l >> 4) & 1) * 8 + (l & 7);
    const int kB = ((l >> 3) & 1) * 8;
    const uint32_t aOff = (uint32_t)(((w * 32 + rA) * PSS + kA) * 2);
    const uint32_t bOff = (uint32_t)((nB * PSS + kB) * 2);
    unsigned int tgt = 0;

    for (int t = 0; t < T_; t++) {
        // ---- Stage h slice: 64 b x 256 k -> hi/lo ----
        __syncthreads();
#pragma unroll
        for (int i = 0; i < 32; i++) {
            int v  = tid + i * 128;        // 0..4095
            int b  = v >> 6;               // 0..63
            int kq = (v & 63) * 4;
            float4 hv = __ldcg((const float4*)(g_hm + b * H_ + kb + kq));
            uint32_t h0, l0, h1, l1;
            split2(hv.x, hv.y, h0, l0);
            split2(hv.z, hv.w, h1, l1);
            uint32_t off = (uint32_t)((b * PSS + kq) * 2);
            *(uint2*)(smem + PS_HH + off) = make_uint2(h0, h1);
            *(uint2*)(smem + PS_HL + off) = make_uint2(l0, l1);
        }
        __syncthreads();

        // ---- Warp GEMM: 32 rows x 64 batches, K=256, 3 passes ----
        float acc[2][8][4];
#pragma unroll
        for (int mt = 0; mt < 2; mt++)
#pragma unroll
            for (int nt = 0; nt < 8; nt++)
#pragma unroll
                for (int q = 0; q < 4; q++) acc[mt][nt][q] = 0.f;

#pragma unroll
        for (int pass = 0; pass < 3; pass++) {
            uint32_t aBase = sb + ((pass == 1) ? PS_WL : PS_WH) + aOff;
            uint32_t bBase = sb + ((pass == 2) ? PS_HL : PS_HH) + bOff;
#pragma unroll 4
            for (int kk = 0; kk < 16; kk++) {
                uint32_t af[2][4];
                ldm4(aBase + kk * 32, af[0]);
                ldm4(aBase + 8448 + kk * 32, af[1]);
                uint32_t bf[8][2];
#pragma unroll
                for (int p = 0; p < 4; p++) {
                    uint32_t r4[4];
                    ldm4(bBase + p * 8448 + kk * 32, r4);
                    bf[p * 2][0] = r4[0]; bf[p * 2][1] = r4[1];
                    bf[p * 2 + 1][0] = r4[2]; bf[p * 2 + 1][1] = r4[3];
                }
#pragma unroll
                for (int mt = 0; mt < 2; mt++)
#pragma unroll
                    for (int nt = 0; nt < 8; nt++)
                        mma16816(acc[mt][nt], af[mt], bf[nt]);
            }
        }

        // ---- Store partials: [ks][rowc][b] ----
#pragma unroll
        for (int mt = 0; mt < 2; mt++) {
            int row = rt * 128 + w * 32 + mt * 16 + (l >> 2);
#pragma unroll
            for (int nt = 0; nt < 8; nt++) {
                int b = nt * 8 + (l & 3) * 2;
                *(float2*)(&g_part[ks][row][b]) =
                    make_float2(acc[mt][nt][0], acc[mt][nt][1]);
                *(float2*)(&g_part[ks][row + 8][b]) =
                    make_float2(acc[mt][nt][2], acc[mt][nt][3]);
            }
        }

        gsync(tgt);

        // ---- Reduce + pointwise: this block owns j in [rt*32+ks*8, +8) ----
#pragma unroll
        for (int u = 0; u < 4; u++) {
            int p  = tid + u * 128;        // 0..511
            int b  = p & 63;
            int jj = p >> 6;               // 0..7
            int j  = rt * 32 + ks * 8 + jj;
            float s[4];
#pragma unroll
            for (int g = 0; g < 4; g++) {
                int rowc = rt * 128 + g * 32 + ks * 8 + jj;
                float a = g_xw[(size_t)(b * T_ + t) * G_ + g * H_ + j];
                a += __ldcg(&g_part[0][rowc][b]);
                a += __ldcg(&g_part[1][rowc][b]);
                a += __ldcg(&g_part[2][rowc][b]);
                a += __ldcg(&g_part[3][rowc][b]);
                s[g] = a;
            }
            const int hidx = b * H_ + j;
            float i_ = 1.f / (1.f + expf(-s[0]));
            float f_ = 1.f / (1.f + expf(-s[1]));
            float gg = tanhf(s[2]);
            float o_ = 1.f / (1.f + expf(-s[3]));
            float cn = fmaf(f_, g_c[hidx], i_ * gg);
            float hn = o_ * tanhf(cn);
            float hm = hn * hid_mask[hidx];
            g_c[hidx]  = cn;
            g_hm[hidx] = hm;
            out[(size_t)(b * T_ + t) * H_ + j] = hn * out_mask[hidx];
            if (t == T_ - 1) {
                out[(size_t)B_ * T_ * H_ + hidx] = hm;                    // h_f
                out[(size_t)B_ * T_ * H_ + (size_t)B_ * H_ + hidx] = cn;  // c_f
            }
        }

        gsync(tgt);
    }
}

// ---------------------------------------------------------------------------
// Launch: 3 graph nodes (init, input GEMM, persistent recurrence)
// ---------------------------------------------------------------------------
extern "C" void kernel_launch(void* const* d_in, const int* in_sizes, int n_in,
                              void* d_out, int out_size)
{
    const float* x        = (const float*)d_in[0];
    const float* Wih      = (const float*)d_in[1];
    const float* Whh      = (const float*)d_in[2];
    const float* bih      = (const float*)d_in[3];
    const float* bhh      = (const float*)d_in[4];
    const float* in_mask  = (const float*)d_in[5];
    const float* hid_mask = (const float*)d_in[6];
    const float* out_mask = (const float*)d_in[7];
    float* out = (float*)d_out;

    static int attr_set = 0;
    if (!attr_set) {
        cudaFuncSetAttribute(k_igemm,   cudaFuncAttributeMaxDynamicSharedMemorySize, IG_SMEM);
        cudaFuncSetAttribute(k_persist, cudaFuncAttributeMaxDynamicSharedMemorySize, PS_SMEM);
        attr_set = 1;
    }

    k_init<<<(B_ * H_ + 255) / 256, 256>>>();
    k_igemm<<<dim3(G_ / 128, (B_ * T_) / 128), 256, IG_SMEM>>>(x, Wih, bih, bhh, in_mask);
    k_persist<<<NBLK, 128, PS_SMEM>>>(Whh, hid_mask, out_mask, out);
}

// round 9
// speedup vs baseline: 2.2981x; 1.2164x over previous
#include <cuda_runtime.h>
#include <cuda_bf16.h>
#include <math.h>
#include <stdint.h>

// Problem constants
#define B_ 64
#define T_ 512
#define D_ 512
#define H_ 1024
#define G_ 4096           // 4*H
#define KS_ 4             // k-split for recurrence
#define KB_ 256           // k per recurrence block (H_/KS_)
#define NBLK 128          // persistent grid (1 block/SM, all resident)

// Device-global scratch (allocation-free per harness rules)
__device__ float g_xw[(size_t)B_ * T_ * G_];     // x @ W_ih^T + bias  [b*T+t][4H]
__device__ __nv_bfloat16 g_hmh[B_ * H_];         // h*hid_mask bf16 hi [b][j]
__device__ __nv_bfloat16 g_hml[B_ * H_];         // h*hid_mask bf16 lo [b][j]
__device__ float g_part[KS_][G_][B_];            // split-k partials [ks][rowc][b]
__device__ unsigned int g_bar;

// ---------------------------- helpers --------------------------------------
__device__ __forceinline__ uint32_t smem_u32(const void* p) {
    uint32_t a;
    asm("{ .reg .u64 t; cvta.to.shared.u64 t, %1; cvt.u32.u64 %0, t; }"
        : "=r"(a) : "l"(p));
    return a;
}
// Split-2 bf16: v = hi + lo (lo itself bf16-rounded); packs pairs (a,b)
__device__ __forceinline__ void split2(float a, float b, uint32_t& hi, uint32_t& lo) {
    __nv_bfloat16 ah = __float2bfloat16(a);
    __nv_bfloat16 bh = __float2bfloat16(b);
    float la = a - __bfloat162float(ah);
    float lb = b - __bfloat162float(bh);
    __nv_bfloat162 h2 = __floats2bfloat162_rn(a, b);
    __nv_bfloat162 l2 = __floats2bfloat162_rn(la, lb);
    hi = *(uint32_t*)&h2;
    lo = *(uint32_t*)&l2;
}
__device__ __forceinline__ void ldm4(uint32_t addr, uint32_t r[4]) {
    asm volatile("ldmatrix.sync.aligned.m8n8.x4.shared.b16 {%0,%1,%2,%3}, [%4];"
        : "=r"(r[0]), "=r"(r[1]), "=r"(r[2]), "=r"(r[3]) : "r"(addr));
}
__device__ __forceinline__ void mma16816(float c[4], const uint32_t a[4],
                                         const uint32_t b[2]) {
    asm volatile(
        "mma.sync.aligned.m16n8k16.row.col.f32.bf16.bf16.f32 "
        "{%0,%1,%2,%3}, {%4,%5,%6,%7}, {%8,%9}, {%0,%1,%2,%3};"
        : "+f"(c[0]), "+f"(c[1]), "+f"(c[2]), "+f"(c[3])
        : "r"(a[0]), "r"(a[1]), "r"(a[2]), "r"(a[3]), "r"(b[0]), "r"(b[1]));
}
// Fast, overflow-safe activations (rel err ~2^-22, irrelevant vs 1e-3 budget)
__device__ __forceinline__ float sigf(float x) {
    return 1.f / (1.f + __expf(-x));     // inf -> 0, 0 -> 1 : safe
}
__device__ __forceinline__ float tanh_fast(float x) {
    float a = fabsf(x);
    float e = __expf(2.f * a);           // may be inf: 2/inf = 0 -> 1 : safe
    float r = 1.f - 2.f / (e + 1.f);
    return copysignf(r, x);
}

// ---------------------------------------------------------------------------
// Init: zero h bf16 state + barrier (65536 threads = exactly the u32 count)
// ---------------------------------------------------------------------------
__global__ void k_init() {
    int i = blockIdx.x * blockDim.x + threadIdx.x;
    if (i < B_ * H_ / 2) ((uint32_t*)g_hmh)[i] = 0u;
    else                 ((uint32_t*)g_hml)[i - B_ * H_ / 2] = 0u;
    if (i == 0) g_bar = 0u;
}

// ---------------------------------------------------------------------------
// Input GEMM (HMMA, split-2 bf16):
//   g_xw[m,n] = sum_d x_masked[m,d] * W_ih[n,d] + (b_ih+b_hh)[n]
// Block: 256 thr (8 warps), tile M=128 x N=128, K chunks of 64 (8 chunks).
// Warp tile 64m x 32n = 4x4 m16n8k16 tiles. 3 split passes. Occupancy 2.
// SMEM row stride 72 bf16 (144B): conflict-free ldmatrix.
// ---------------------------------------------------------------------------
#define IG_AH   0
#define IG_AL   18432
#define IG_BH   36864
#define IG_BL   55296
#define IG_BIAS 73728
#define IG_SMEM 74240

__global__ __launch_bounds__(256, 2) void k_igemm(
    const float* __restrict__ x, const float* __restrict__ Wih,
    const float* __restrict__ bih, const float* __restrict__ bhh,
    const float* __restrict__ in_mask)
{
    extern __shared__ __align__(16) char smem[];
    const uint32_t sb = smem_u32(smem);
    const int tid = threadIdx.x;
    const int l   = tid & 31;
    const int w   = tid >> 5;
    const int wy  = w >> 2;         // 0..1 (m half)
    const int wx  = w & 3;          // 0..3 (n quarter)
    const int n0  = blockIdx.x * 128;
    const int m0  = blockIdx.y * 128;

    float* sBias = (float*)(smem + IG_BIAS);
    if (tid < 128) sBias[tid] = bih[n0 + tid] + bhh[n0 + tid];

    // ldmatrix lane-address components
    const int rA = ((l >> 3) & 1) * 8 + (l & 7);
    const int kA = (l >> 4) * 8;
    const int nB = ((l >> 4) & 1) * 8 + (l & 7);
    const int kB = ((l >> 3) & 1) * 8;
    const uint32_t aOff = (uint32_t)(((wy * 64 + rA) * 72 + kA) * 2);
    const uint32_t bOff = (uint32_t)(((wx * 32 + nB) * 72 + kB) * 2);

    float acc[4][4][4] = {};

    for (int ch = 0; ch < 8; ch++) {
        const int kk = ch * 64;
        __syncthreads();
        // Stage x tile: 128 rows x 64 k -> hi/lo
#pragma unroll
        for (int i = 0; i < 8; i++) {
            int v = tid + i * 256;
            int r = v >> 4;
            int kq = (v & 15) * 4;
            int m = m0 + r;
            float4 xv = *(const float4*)(x + (size_t)m * D_ + kk + kq);
            if ((m & (T_ - 1)) == 0) {
                const float* im = in_mask + (m >> 9) * D_ + kk + kq;
                xv.x *= im[0]; xv.y *= im[1]; xv.z *= im[2]; xv.w *= im[3];
            }
            uint32_t h0, l0, h1, l1;
            split2(xv.x, xv.y, h0, l0);
            split2(xv.z, xv.w, h1, l1);
            uint32_t off = (uint32_t)((r * 72 + kq) * 2);
            *(uint2*)(smem + IG_AH + off) = make_uint2(h0, h1);
            *(uint2*)(smem + IG_AL + off) = make_uint2(l0, l1);
        }
        // Stage Wih tile: 128 rows x 64 k -> hi/lo
#pragma unroll
        for (int i = 0; i < 8; i++) {
            int v = tid + i * 256;
            int r = v >> 4;
            int kq = (v & 15) * 4;
            float4 wv = *(const float4*)(Wih + (size_t)(n0 + r) * D_ + kk + kq);
            uint32_t h0, l0, h1, l1;
            split2(wv.x, wv.y, h0, l0);
            split2(wv.z, wv.w, h1, l1);
            uint32_t off = (uint32_t)((r * 72 + kq) * 2);
            *(uint2*)(smem + IG_BH + off) = make_uint2(h0, h1);
            *(uint2*)(smem + IG_BL + off) = make_uint2(l0, l1);
        }
        __syncthreads();

#pragma unroll
        for (int pass = 0; pass < 3; pass++) {
            uint32_t aBase = sb + ((pass == 1) ? IG_AL : IG_AH) + aOff;
            uint32_t bBase = sb + ((pass == 2) ? IG_BL : IG_BH) + bOff;
#pragma unroll
            for (int ks = 0; ks < 4; ks++) {
                uint32_t af[4][4];
#pragma unroll
                for (int mt = 0; mt < 4; mt++)
                    ldm4(aBase + mt * 2304 + ks * 32, af[mt]);
                uint32_t bf[4][2];
#pragma unroll
                for (int p = 0; p < 2; p++) {
                    uint32_t r4[4];
                    ldm4(bBase + p * 2304 + ks * 32, r4);
                    bf[p * 2][0] = r4[0]; bf[p * 2][1] = r4[1];
                    bf[p * 2 + 1][0] = r4[2]; bf[p * 2 + 1][1] = r4[3];
                }
#pragma unroll
                for (int mt = 0; mt < 4; mt++)
#pragma unroll
                    for (int nt = 0; nt < 4; nt++)
                        mma16816(acc[mt][nt], af[mt], bf[nt]);
            }
        }
    }

    // Epilogue: bias + store
#pragma unroll
    for (int mt = 0; mt < 4; mt++) {
        int mrow = m0 + wy * 64 + mt * 16 + (l >> 2);
#pragma unroll
        for (int nt = 0; nt < 4; nt++) {
            int nl = wx * 32 + nt * 8 + (l & 3) * 2;
            float b0 = sBias[nl], b1 = sBias[nl + 1];
            *(float2*)(g_xw + (size_t)mrow * G_ + n0 + nl) =
                make_float2(acc[mt][nt][0] + b0, acc[mt][nt][1] + b1);
            *(float2*)(g_xw + (size_t)(mrow + 8) * G_ + n0 + nl) =
                make_float2(acc[mt][nt][2] + b0, acc[mt][nt][3] + b1);
        }
    }
}

// ---------------------------------------------------------------------------
// Grid barrier
// ---------------------------------------------------------------------------
__device__ __forceinline__ void gsync(unsigned int& tgt) {
    __threadfence();
    __syncthreads();
    if (threadIdx.x == 0) {
        atomicAdd(&g_bar, 1u);
        tgt += NBLK;
        while (*(volatile unsigned int*)&g_bar < tgt) { __nanosleep(64); }
        __threadfence();
    }
    __syncthreads();
}

// ---------------------------------------------------------------------------
// Persistent recurrence (HMMA). Grid 128 blocks x 256 threads (8 warps).
// Block (rt = bid>>2, ks = bid&3): A = 128 gathered gate-rows
//   grow(lr) = (lr>>5)*H + rt*32 + (lr&31),  k-slice [ks*256, +256).
// W slice bf16 hi/lo SMEM ONCE (132 KB, resident). h pre-split in global
// (g_hmh/g_hml) by the pointwise phase -> staging is a pure copy.
// c / masks live in registers (block owns j in [rt*32+ks*8, +8), all b).
// Per step: copy h slice -> warp GEMM (16 rows x 64 b, 3 passes) -> partials
//   -> prefetch xw -> gsync -> reduce+pointwise -> gsync.
// SMEM row stride 264 bf16 (528B): conflict-free ldmatrix.
// ---------------------------------------------------------------------------
#define PSS     264
#define PS_WH   0
#define PS_WL   67584
#define PS_HH   135168
#define PS_HL   168960
#define PS_SMEM 202752

__global__ __launch_bounds__(256, 1) void k_persist(
    const float* __restrict__ Whh,
    const float* __restrict__ hid_mask,
    const float* __restrict__ out_mask,
    float* __restrict__ out)
{
    extern __shared__ __align__(16) char smem[];
    const uint32_t sb = smem_u32(smem);
    const int tid = threadIdx.x;
    const int l   = tid & 31;
    const int w   = tid >> 5;
    const int bid = blockIdx.x;
    const int rt  = bid >> 2;
    const int ks  = bid & 3;
    const int kb  = ks * KB_;

    // ---- Convert + stage W slice once: 128 gathered rows x 256 k ----
#pragma unroll
    for (int i = 0; i < 32; i++) {
        int v  = tid + i * 256;            // 0..8191
        int lr = v >> 6;                   // 0..127
        int kq = (v & 63) * 4;             // 0..252
        int grow = (lr >> 5) * H_ + rt * 32 + (lr & 31);
        float4 wv = *(const float4*)(Whh + (size_t)grow * H_ + kb + kq);
        uint32_t h0, l0, h1, l1;
        split2(wv.x, wv.y, h0, l0);
        split2(wv.z, wv.w, h1, l1);
        uint32_t off = (uint32_t)((lr * PSS + kq) * 2);
        *(uint2*)(smem + PS_WH + off) = make_uint2(h0, h1);
        *(uint2*)(smem + PS_WL + off) = make_uint2(l0, l1);
    }

    // ---- Register-resident state for the owned (b, j) elements ----
    float c_reg[2] = {0.f, 0.f};
    float hmk[2], omk[2];
    int   bb[2], jj_[2];
#pragma unroll
    for (int u = 0; u < 2; u++) {
        int p  = tid + u * 256;            // 0..511
        bb[u]  = p & 63;
        jj_[u] = p >> 6;                   // 0..7
        int j  = rt * 32 + ks * 8 + jj_[u];
        hmk[u] = hid_mask[bb[u] * H_ + j];
        omk[u] = out_mask[bb[u] * H_ + j];
    }

    // ldmatrix lane-address components
    const int rA = ((l >> 3) & 1) * 8 + (l & 7);
    const int kA = (l >> 4) * 8;
    const int nB = ((l >> 4) & 1) * 8 + (l & 7);
    const int kB = ((l >> 3) & 1) * 8;
    const uint32_t aOff = (uint32_t)(((w * 16 + rA) * PSS + kA) * 2);
    const uint32_t bOff = (uint32_t)((nB * PSS + kB) * 2);
    unsigned int tgt = 0;

    for (int t = 0; t < T_; t++) {
        // ---- Stage h slice (pure copy of pre-split bf16): 64 b x 256 k ----
        __syncthreads();
#pragma unroll
        for (int i = 0; i < 8; i++) {
            int v  = tid + i * 256;        // 0..2047
            int b  = v >> 5;               // 0..63
            int kq = (v & 31) * 8;         // 0..248
            uint4 hv = __ldcg((const uint4*)(g_hmh + (size_t)b * H_ + kb + kq));
            uint4 lv = __ldcg((const uint4*)(g_hml + (size_t)b * H_ + kb + kq));
            uint32_t off = (uint32_t)((b * PSS + kq) * 2);
            *(uint4*)(smem + PS_HH + off) = hv;
            *(uint4*)(smem + PS_HL + off) = lv;
        }
        __syncthreads();

        // ---- Warp GEMM: 16 rows x 64 batches, K=256, 3 passes ----
        float acc[8][4];
#pragma unroll
        for (int nt = 0; nt < 8; nt++)
#pragma unroll
            for (int q = 0; q < 4; q++) acc[nt][q] = 0.f;

#pragma unroll
        for (int pass = 0; pass < 3; pass++) {
            uint32_t aBase = sb + ((pass == 1) ? PS_WL : PS_WH) + aOff;
            uint32_t bBase = sb + ((pass == 2) ? PS_HL : PS_HH) + bOff;
#pragma unroll 4
            for (int kk = 0; kk < 16; kk++) {
                uint32_t af[4];
                ldm4(aBase + kk * 32, af);
                uint32_t bf[8][2];
#pragma unroll
                for (int p = 0; p < 4; p++) {
                    uint32_t r4[4];
                    ldm4(bBase + p * 8448 + kk * 32, r4);
                    bf[p * 2][0] = r4[0]; bf[p * 2][1] = r4[1];
                    bf[p * 2 + 1][0] = r4[2]; bf[p * 2 + 1][1] = r4[3];
                }
#pragma unroll
                for (int nt = 0; nt < 8; nt++)
                    mma16816(acc[nt], af, bf[nt]);
            }
        }

        // ---- Store partials: [ks][rowc][b] ----
        {
            int row = rt * 128 + w * 16 + (l >> 2);
#pragma unroll
            for (int nt = 0; nt < 8; nt++) {
                int b = nt * 8 + (l & 3) * 2;
                *(float2*)(&g_part[ks][row][b]) = make_float2(acc[nt][0], acc[nt][1]);
                *(float2*)(&g_part[ks][row + 8][b]) = make_float2(acc[nt][2], acc[nt][3]);
            }
        }

        // ---- Prefetch xw(t) for the owned elements (hides under barrier) ----
        float xwv[2][4];
#pragma unroll
        for (int u = 0; u < 2; u++) {
            int j = rt * 32 + ks * 8 + jj_[u];
#pragma unroll
            for (int g = 0; g < 4; g++)
                xwv[u][g] = g_xw[(size_t)(bb[u] * T_ + t) * G_ + g * H_ + j];
        }

        gsync(tgt);

        // ---- Reduce + pointwise ----
#pragma unroll
        for (int u = 0; u < 2; u++) {
            int b  = bb[u];
            int jj = jj_[u];
            int j  = rt * 32 + ks * 8 + jj;
            float s[4];
#pragma unroll
            for (int g = 0; g < 4; g++) {
                int rowc = rt * 128 + g * 32 + ks * 8 + jj;
                float a = xwv[u][g];
                a += __ldcg(&g_part[0][rowc][b]);
                a += __ldcg(&g_part[1][rowc][b]);
                a += __ldcg(&g_part[2][rowc][b]);
                a += __ldcg(&g_part[3][rowc][b]);
                s[g] = a;
            }
            float i_ = sigf(s[0]);
            float f_ = sigf(s[1]);
            float gg = tanh_fast(s[2]);
            float o_ = sigf(s[3]);
            float cn = fmaf(f_, c_reg[u], i_ * gg);
            float hn = o_ * tanh_fast(cn);
            float hm = hn * hmk[u];
            c_reg[u] = cn;
            // pre-split h for the next step's staging
            __nv_bfloat16 hh = __float2bfloat16(hm);
            __nv_bfloat16 hl = __float2bfloat16(hm - __bfloat162float(hh));
            g_hmh[b * H_ + j] = hh;
            g_hml[b * H_ + j] = hl;
            out[(size_t)(b * T_ + t) * H_ + j] = hn * omk[u];
            if (t == T_ - 1) {
                int hidx = b * H_ + j;
                out[(size_t)B_ * T_ * H_ + hidx] = hm;                    // h_f
                out[(size_t)B_ * T_ * H_ + (size_t)B_ * H_ + hidx] = cn;  // c_f
            }
        }

        gsync(tgt);
    }
}

// ---------------------------------------------------------------------------
// Launch: 3 graph nodes (init, input GEMM, persistent recurrence)
// ---------------------------------------------------------------------------
extern "C" void kernel_launch(void* const* d_in, const int* in_sizes, int n_in,
                              void* d_out, int out_size)
{
    const float* x        = (const float*)d_in[0];
    const float* Wih      = (const float*)d_in[1];
    const float* Whh      = (const float*)d_in[2];
    const float* bih      = (const float*)d_in[3];
    const float* bhh      = (const float*)d_in[4];
    const float* in_mask  = (const float*)d_in[5];
    const float* hid_mask = (const float*)d_in[6];
    const float* out_mask = (const float*)d_in[7];
    float* out = (float*)d_out;

    static int attr_set = 0;
    if (!attr_set) {
        cudaFuncSetAttribute(k_igemm,   cudaFuncAttributeMaxDynamicSharedMemorySize, IG_SMEM);
        cudaFuncSetAttribute(k_persist, cudaFuncAttributeMaxDynamicSharedMemorySize, PS_SMEM);
        attr_set = 1;
    }

    k_init<<<256, 256>>>();
    k_igemm<<<dim3(G_ / 128, (B_ * T_) / 128), 256, IG_SMEM>>>(x, Wih, bih, bhh, in_mask);
    k_persist<<<NBLK, 256, PS_SMEM>>>(Whh, hid_mask, out_mask, out);
}

// round 10
// speedup vs baseline: 2.5624x; 1.1150x over previous
#include <cuda_runtime.h>
#include <cuda_bf16.h>
#include <math.h>
#include <stdint.h>

// Problem constants
#define B_ 64
#define T_ 512
#define D_ 512
#define H_ 1024
#define G_ 4096           // 4*H
#define KS_ 4             // k-split for recurrence
#define KB_ 256           // k per recurrence block (H_/KS_)
#define NBLK 128          // persistent grid (1 block/SM, all resident)

// Device-global scratch (allocation-free per harness rules)
__device__ float g_xw[(size_t)B_ * T_ * G_];     // x @ W_ih^T + bias  [b*T+t][4H]
__device__ __nv_bfloat16 g_hmh[B_ * H_];         // h*hid_mask bf16 hi [b][j]
__device__ __nv_bfloat16 g_hml[B_ * H_];         // h*hid_mask bf16 lo [b][j]
__device__ float g_part[KS_][G_][B_];            // split-k partials [ks][rowc][b]
__device__ unsigned int g_bar;

// ---------------------------- helpers --------------------------------------
__device__ __forceinline__ uint32_t smem_u32(const void* p) {
    uint32_t a;
    asm("{ .reg .u64 t; cvta.to.shared.u64 t, %1; cvt.u32.u64 %0, t; }"
        : "=r"(a) : "l"(p));
    return a;
}
// Split-2 bf16: v = hi + lo (lo itself bf16-rounded); packs pairs (a,b)
__device__ __forceinline__ void split2(float a, float b, uint32_t& hi, uint32_t& lo) {
    __nv_bfloat16 ah = __float2bfloat16(a);
    __nv_bfloat16 bh = __float2bfloat16(b);
    float la = a - __bfloat162float(ah);
    float lb = b - __bfloat162float(bh);
    __nv_bfloat162 h2 = __floats2bfloat162_rn(a, b);
    __nv_bfloat162 l2 = __floats2bfloat162_rn(la, lb);
    hi = *(uint32_t*)&h2;
    lo = *(uint32_t*)&l2;
}
__device__ __forceinline__ void ldm4(uint32_t addr, uint32_t r[4]) {
    asm volatile("ldmatrix.sync.aligned.m8n8.x4.shared.b16 {%0,%1,%2,%3}, [%4];"
        : "=r"(r[0]), "=r"(r[1]), "=r"(r[2]), "=r"(r[3]) : "r"(addr));
}
__device__ __forceinline__ void mma16816(float c[4], const uint32_t a[4],
                                         const uint32_t b[2]) {
    asm volatile(
        "mma.sync.aligned.m16n8k16.row.col.f32.bf16.bf16.f32 "
        "{%0,%1,%2,%3}, {%4,%5,%6,%7}, {%8,%9}, {%0,%1,%2,%3};"
        : "+f"(c[0]), "+f"(c[1]), "+f"(c[2]), "+f"(c[3])
        : "r"(a[0]), "r"(a[1]), "r"(a[2]), "r"(a[3]), "r"(b[0]), "r"(b[1]));
}
__device__ __forceinline__ void cp16(uint32_t smem_dst, const void* gsrc) {
    asm volatile("cp.async.cg.shared.global [%0], [%1], 16;"
                 :: "r"(smem_dst), "l"(gsrc) : "memory");
}
// Fast, overflow-safe activations (rel err ~2^-22, irrelevant vs 1e-3 budget)
__device__ __forceinline__ float sigf(float x) {
    return 1.f / (1.f + __expf(-x));
}
__device__ __forceinline__ float tanh_fast(float x) {
    float a = fabsf(x);
    float e = __expf(2.f * a);
    float r = 1.f - 2.f / (e + 1.f);
    return copysignf(r, x);
}

// ---------------------------------------------------------------------------
// Init: zero h bf16 state + barrier
// ---------------------------------------------------------------------------
__global__ void k_init() {
    int i = blockIdx.x * blockDim.x + threadIdx.x;
    if (i < B_ * H_ / 2) ((uint32_t*)g_hmh)[i] = 0u;
    else                 ((uint32_t*)g_hml)[i - B_ * H_ / 2] = 0u;
    if (i == 0) g_bar = 0u;
}

// ---------------------------------------------------------------------------
// Input GEMM (HMMA, split-2 bf16):
//   g_xw[m,n] = sum_d x_masked[m,d] * W_ih[n,d] + (b_ih+b_hh)[n]
// Block: 256 thr (8 warps), tile M=128 x N=128, K chunks of 64 (8 chunks).
// Warp tile 64m x 32n = 4x4 m16n8k16 tiles. 3 split passes. Occupancy 2.
// SMEM row stride 72 bf16 (144B): conflict-free ldmatrix.
// ---------------------------------------------------------------------------
#define IG_AH   0
#define IG_AL   18432
#define IG_BH   36864
#define IG_BL   55296
#define IG_BIAS 73728
#define IG_SMEM 74240

__global__ __launch_bounds__(256, 2) void k_igemm(
    const float* __restrict__ x, const float* __restrict__ Wih,
    const float* __restrict__ bih, const float* __restrict__ bhh,
    const float* __restrict__ in_mask)
{
    extern __shared__ __align__(16) char smem[];
    const uint32_t sb = smem_u32(smem);
    const int tid = threadIdx.x;
    const int l   = tid & 31;
    const int w   = tid >> 5;
    const int wy  = w >> 2;         // 0..1 (m half)
    const int wx  = w & 3;          // 0..3 (n quarter)
    const int n0  = blockIdx.x * 128;
    const int m0  = blockIdx.y * 128;

    float* sBias = (float*)(smem + IG_BIAS);
    if (tid < 128) sBias[tid] = bih[n0 + tid] + bhh[n0 + tid];

    // ldmatrix lane-address components
    const int rA = ((l >> 3) & 1) * 8 + (l & 7);
    const int kA = (l >> 4) * 8;
    const int nB = ((l >> 4) & 1) * 8 + (l & 7);
    const int kB = ((l >> 3) & 1) * 8;
    const uint32_t aOff = (uint32_t)(((wy * 64 + rA) * 72 + kA) * 2);
    const uint32_t bOff = (uint32_t)(((wx * 32 + nB) * 72 + kB) * 2);

    float acc[4][4][4] = {};

    for (int ch = 0; ch < 8; ch++) {
        const int kk = ch * 64;
        __syncthreads();
        // Stage x tile: 128 rows x 64 k -> hi/lo
#pragma unroll
        for (int i = 0; i < 8; i++) {
            int v = tid + i * 256;
            int r = v >> 4;
            int kq = (v & 15) * 4;
            int m = m0 + r;
            float4 xv = *(const float4*)(x + (size_t)m * D_ + kk + kq);
            if ((m & (T_ - 1)) == 0) {
                const float* im = in_mask + (m >> 9) * D_ + kk + kq;
                xv.x *= im[0]; xv.y *= im[1]; xv.z *= im[2]; xv.w *= im[3];
            }
            uint32_t h0, l0, h1, l1;
            split2(xv.x, xv.y, h0, l0);
            split2(xv.z, xv.w, h1, l1);
            uint32_t off = (uint32_t)((r * 72 + kq) * 2);
            *(uint2*)(smem + IG_AH + off) = make_uint2(h0, h1);
            *(uint2*)(smem + IG_AL + off) = make_uint2(l0, l1);
        }
        // Stage Wih tile: 128 rows x 64 k -> hi/lo
#pragma unroll
        for (int i = 0; i < 8; i++) {
            int v = tid + i * 256;
            int r = v >> 4;
            int kq = (v & 15) * 4;
            float4 wv = *(const float4*)(Wih + (size_t)(n0 + r) * D_ + kk + kq);
            uint32_t h0, l0, h1, l1;
            split2(wv.x, wv.y, h0, l0);
            split2(wv.z, wv.w, h1, l1);
            uint32_t off = (uint32_t)((r * 72 + kq) * 2);
            *(uint2*)(smem + IG_BH + off) = make_uint2(h0, h1);
            *(uint2*)(smem + IG_BL + off) = make_uint2(l0, l1);
        }
        __syncthreads();

#pragma unroll
        for (int pass = 0; pass < 3; pass++) {
            uint32_t aBase = sb + ((pass == 1) ? IG_AL : IG_AH) + aOff;
            uint32_t bBase = sb + ((pass == 2) ? IG_BL : IG_BH) + bOff;
#pragma unroll
            for (int ks = 0; ks < 4; ks++) {
                uint32_t af[4][4];
#pragma unroll
                for (int mt = 0; mt < 4; mt++)
                    ldm4(aBase + mt * 2304 + ks * 32, af[mt]);
                uint32_t bf[4][2];
#pragma unroll
                for (int p = 0; p < 2; p++) {
                    uint32_t r4[4];
                    ldm4(bBase + p * 2304 + ks * 32, r4);
                    bf[p * 2][0] = r4[0]; bf[p * 2][1] = r4[1];
                    bf[p * 2 + 1][0] = r4[2]; bf[p * 2 + 1][1] = r4[3];
                }
#pragma unroll
                for (int mt = 0; mt < 4; mt++)
#pragma unroll
                    for (int nt = 0; nt < 4; nt++)
                        mma16816(acc[mt][nt], af[mt], bf[nt]);
            }
        }
    }

    // Epilogue: bias + store
#pragma unroll
    for (int mt = 0; mt < 4; mt++) {
        int mrow = m0 + wy * 64 + mt * 16 + (l >> 2);
#pragma unroll
        for (int nt = 0; nt < 4; nt++) {
            int nl = wx * 32 + nt * 8 + (l & 3) * 2;
            float b0 = sBias[nl], b1 = sBias[nl + 1];
            *(float2*)(g_xw + (size_t)mrow * G_ + n0 + nl) =
                make_float2(acc[mt][nt][0] + b0, acc[mt][nt][1] + b1);
            *(float2*)(g_xw + (size_t)(mrow + 8) * G_ + n0 + nl) =
                make_float2(acc[mt][nt][2] + b0, acc[mt][nt][3] + b1);
        }
    }
}

// ---------------------------------------------------------------------------
// Cheap grid barrier (CG grid.sync pattern: block bar + one-thread gpu fence)
// ---------------------------------------------------------------------------
__device__ __forceinline__ void gsync(unsigned int& tgt) {
    __syncthreads();
    if (threadIdx.x == 0) {
        asm volatile("fence.acq_rel.gpu;" ::: "memory");
        atomicAdd(&g_bar, 1u);
        tgt += NBLK;
        while (*(volatile unsigned int*)&g_bar < tgt) {}
        asm volatile("fence.acq_rel.gpu;" ::: "memory");
    }
    __syncthreads();
}

// ---------------------------------------------------------------------------
// Persistent recurrence (HMMA). Grid 128 blocks x 256 threads (8 warps).
// Block (rt = bid>>2, ks = bid&3): A = 128 gathered gate-rows
//   grow(lr) = (lr>>5)*H + rt*32 + (lr&31),  k-slice [ks*256, +256).
// W slice bf16 hi/lo SMEM ONCE (132 KB, resident). h pre-split in global
// (g_hmh/g_hml) by the pointwise phase -> staging is a cp.async copy.
// c / masks in registers; thread owns (b, {2*jp, 2*jp+1}) -> vector stores.
// Per step: cp.async h -> warp GEMM (16 rows x 64 b, 3 passes) -> prefetch xw
//   -> store partials -> gsync -> reduce+pointwise -> gsync (skipped at t=T-1).
// SMEM row stride 264 bf16 (528B): conflict-free ldmatrix.
// ---------------------------------------------------------------------------
#define PSS     264
#define PS_WH   0
#define PS_WL   67584
#define PS_HH   135168
#define PS_HL   168960
#define PS_SMEM 202752

__global__ __launch_bounds__(256, 1) void k_persist(
    const float* __restrict__ Whh,
    const float* __restrict__ hid_mask,
    const float* __restrict__ out_mask,
    float* __restrict__ out)
{
    extern __shared__ __align__(16) char smem[];
    const uint32_t sb = smem_u32(smem);
    const int tid = threadIdx.x;
    const int l   = tid & 31;
    const int w   = tid >> 5;
    const int bid = blockIdx.x;
    const int rt  = bid >> 2;
    const int ks  = bid & 3;
    const int kb  = ks * KB_;

    // ---- Convert + stage W slice once: 128 gathered rows x 256 k ----
#pragma unroll
    for (int i = 0; i < 32; i++) {
        int v  = tid + i * 256;            // 0..8191
        int lr = v >> 6;                   // 0..127
        int kq = (v & 63) * 4;             // 0..252
        int grow = (lr >> 5) * H_ + rt * 32 + (lr & 31);
        float4 wv = *(const float4*)(Whh + (size_t)grow * H_ + kb + kq);
        uint32_t h0, l0, h1, l1;
        split2(wv.x, wv.y, h0, l0);
        split2(wv.z, wv.w, h1, l1);
        uint32_t off = (uint32_t)((lr * PSS + kq) * 2);
        *(uint2*)(smem + PS_WH + off) = make_uint2(h0, h1);
        *(uint2*)(smem + PS_WL + off) = make_uint2(l0, l1);
    }

    // ---- Register-resident state: thread owns (b, j0) and (b, j0+1) ----
    const int bb = tid & 63;               // batch
    const int jp = tid >> 6;               // 0..3 -> j pair
    const int j0 = rt * 32 + ks * 8 + jp * 2;
    const int hidx0 = bb * H_ + j0;
    float c_reg[2] = {0.f, 0.f};
    float2 hmk = *(const float2*)(hid_mask + hidx0);
    float2 omk = *(const float2*)(out_mask + hidx0);

    // ldmatrix lane-address components
    const int rA = ((l >> 3) & 1) * 8 + (l & 7);
    const int kA = (l >> 4) * 8;
    const int nB = ((l >> 4) & 1) * 8 + (l & 7);
    const int kB = ((l >> 3) & 1) * 8;
    const uint32_t aOff = (uint32_t)(((w * 16 + rA) * PSS + kA) * 2);
    const uint32_t bOff = (uint32_t)((nB * PSS + kB) * 2);
    unsigned int tgt = 0;

    for (int t = 0; t < T_; t++) {
        // ---- Stage h slice via cp.async: 64 b x 256 k (hi + lo) ----
        __syncthreads();
#pragma unroll
        for (int i = 0; i < 8; i++) {
            int v  = tid + i * 256;        // 0..2047
            int b  = v >> 5;               // 0..63
            int kq = (v & 31) * 8;         // 0..248
            uint32_t off = (uint32_t)((b * PSS + kq) * 2);
            cp16(sb + PS_HH + off, g_hmh + (size_t)b * H_ + kb + kq);
            cp16(sb + PS_HL + off, g_hml + (size_t)b * H_ + kb + kq);
        }
        asm volatile("cp.async.wait_all;" ::: "memory");
        __syncthreads();

        // ---- Warp GEMM: 16 rows x 64 batches, K=256, 3 passes ----
        float acc[8][4];
#pragma unroll
        for (int nt = 0; nt < 8; nt++)
#pragma unroll
            for (int q = 0; q < 4; q++) acc[nt][q] = 0.f;

#pragma unroll
        for (int pass = 0; pass < 3; pass++) {
            uint32_t aBase = sb + ((pass == 1) ? PS_WL : PS_WH) + aOff;
            uint32_t bBase = sb + ((pass == 2) ? PS_HL : PS_HH) + bOff;
#pragma unroll 4
            for (int kk = 0; kk < 16; kk++) {
                uint32_t af[4];
                ldm4(aBase + kk * 32, af);
                uint32_t bf[8][2];
#pragma unroll
                for (int p = 0; p < 4; p++) {
                    uint32_t r4[4];
                    ldm4(bBase + p * 8448 + kk * 32, r4);
                    bf[p * 2][0] = r4[0]; bf[p * 2][1] = r4[1];
                    bf[p * 2 + 1][0] = r4[2]; bf[p * 2 + 1][1] = r4[3];
                }
#pragma unroll
                for (int nt = 0; nt < 8; nt++)
                    mma16816(acc[nt], af, bf[nt]);
            }
        }

        // ---- Prefetch xw(t) early (hides DRAM latency under stores+barrier)
        float xwv[2][4];
#pragma unroll
        for (int u = 0; u < 2; u++)
#pragma unroll
            for (int g = 0; g < 4; g++)
                xwv[u][g] = g_xw[(size_t)(bb * T_ + t) * G_ + g * H_ + j0 + u];

        // ---- Store partials: [ks][rowc][b] ----
        {
            int row = rt * 128 + w * 16 + (l >> 2);
#pragma unroll
            for (int nt = 0; nt < 8; nt++) {
                int b = nt * 8 + (l & 3) * 2;
                *(float2*)(&g_part[ks][row][b]) = make_float2(acc[nt][0], acc[nt][1]);
                *(float2*)(&g_part[ks][row + 8][b]) = make_float2(acc[nt][2], acc[nt][3]);
            }
        }

        gsync(tgt);

        // ---- Reduce + pointwise (2 adjacent j per thread) ----
        float cn[2], hn[2], hm[2];
#pragma unroll
        for (int u = 0; u < 2; u++) {
            float s[4];
#pragma unroll
            for (int g = 0; g < 4; g++) {
                int rowc = rt * 128 + g * 32 + ks * 8 + jp * 2 + u;
                float a = xwv[u][g];
                a += __ldcg(&g_part[0][rowc][bb]);
                a += __ldcg(&g_part[1][rowc][bb]);
                a += __ldcg(&g_part[2][rowc][bb]);
                a += __ldcg(&g_part[3][rowc][bb]);
                s[g] = a;
            }
            float i_ = sigf(s[0]);
            float f_ = sigf(s[1]);
            float gg = tanh_fast(s[2]);
            float o_ = sigf(s[3]);
            cn[u] = fmaf(f_, c_reg[u], i_ * gg);
            hn[u] = o_ * tanh_fast(cn[u]);
            hm[u] = hn[u] * ((u == 0) ? hmk.x : hmk.y);
            c_reg[u] = cn[u];
        }
        // Vectorized state + output stores (adjacent j)
        {
            __nv_bfloat16 h0 = __float2bfloat16(hm[0]);
            __nv_bfloat16 h1 = __float2bfloat16(hm[1]);
            __nv_bfloat16 l0 = __float2bfloat16(hm[0] - __bfloat162float(h0));
            __nv_bfloat16 l1 = __float2bfloat16(hm[1] - __bfloat162float(h1));
            *(__nv_bfloat162*)(g_hmh + hidx0) = __nv_bfloat162(h0, h1);
            *(__nv_bfloat162*)(g_hml + hidx0) = __nv_bfloat162(l0, l1);
            *(float2*)(out + (size_t)(bb * T_ + t) * H_ + j0) =
                make_float2(hn[0] * omk.x, hn[1] * omk.y);
            if (t == T_ - 1) {
                *(float2*)(out + (size_t)B_ * T_ * H_ + hidx0) =
                    make_float2(hm[0], hm[1]);                                 // h_f
                *(float2*)(out + (size_t)B_ * T_ * H_ + (size_t)B_ * H_ + hidx0) =
                    make_float2(cn[0], cn[1]);                                 // c_f
            }
        }

        if (t + 1 < T_) gsync(tgt);
    }
}

// ---------------------------------------------------------------------------
// Launch: 3 graph nodes (init, input GEMM, persistent recurrence)
// ---------------------------------------------------------------------------
extern "C" void kernel_launch(void* const* d_in, const int* in_sizes, int n_in,
                              void* d_out, int out_size)
{
    const float* x        = (const float*)d_in[0];
    const float* Wih      = (const float*)d_in[1];
    const float* Whh      = (const float*)d_in[2];
    const float* bih      = (const float*)d_in[3];
    const float* bhh      = (const float*)d_in[4];
    const float* in_mask  = (const float*)d_in[5];
    const float* hid_mask = (const float*)d_in[6];
    const float* out_mask = (const float*)d_in[7];
    float* out = (float*)d_out;

    static int attr_set = 0;
    if (!attr_set) {
        cudaFuncSetAttribute(k_igemm,   cudaFuncAttributeMaxDynamicSharedMemorySize, IG_SMEM);
        cudaFuncSetAttribute(k_persist, cudaFuncAttributeMaxDynamicSharedMemorySize, PS_SMEM);
        attr_set = 1;
    }

    k_init<<<256, 256>>>();
    k_igemm<<<dim3(G_ / 128, (B_ * T_) / 128), 256, IG_SMEM>>>(x, Wih, bih, bhh, in_mask);
    k_persist<<<NBLK, 256, PS_SMEM>>>(Whh, hid_mask, out_mask, out);
}